// round 1
// baseline (speedup 1.0000x reference)
#include <cuda_runtime.h>
#include <math.h>

// Problem shapes (fixed by setup_inputs in the reference):
//   images: [N=4, C=256, H=50, W=50] float32
//   rois:   [R=256, 4] float32  (x1,y1,x2,y2 normalized)
//   roi_idx:[R=256] int32
//   out:    [R=256, C=256, S=7, S=7] float32
#define NN 4
#define CC 256
#define HH 50
#define WW 50
#define RR 256
#define SS 7

__global__ __launch_bounds__(256)
void SlowROIPool_43705587204143_kernel(const float* __restrict__ images,
                                       const float* __restrict__ rois,
                                       const int*   __restrict__ roi_idx,
                                       float*       __restrict__ out) {
    const int total = RR * CC * SS * SS;
    int o = blockIdx.x * blockDim.x + threadIdx.x;
    if (o >= total) return;

    // o = ((r*C + c)*S + i)*S + j
    int b  = o % (SS * SS);
    int rc = o / (SS * SS);
    int c  = rc % CC;
    int r  = rc / CC;
    int i  = b / SS;
    int j  = b % SS;

    // ROI geometry — identical fp32 ops to the reference (floor/ceil of x*50).
    float4 rb = __ldg((const float4*)rois + r);
    int x1 = (int)floorf(rb.x * (float)WW);
    int y1 = (int)floorf(rb.y * (float)HH);
    int x2 = (int)ceilf (rb.z * (float)WW);
    int y2 = (int)ceilf (rb.w * (float)HH);
    int sw = x2 - x1;
    int sh = y2 - y1;

    // PyTorch adaptive bins: start = lo + floor(i*sz/S), end = lo + ceil((i+1)*sz/S)
    int ws = x1 + (j * sw) / SS;
    int we = x1 + ((j + 1) * sw + SS - 1) / SS;
    int hs = y1 + (i * sh) / SS;
    int he = y1 + ((i + 1) * sh + SS - 1) / SS;

    int n = __ldg(roi_idx + r);
    const float* base = images + ((size_t)(n * CC + c)) * (HH * WW);

    float m = -3.402823466e38f;
    for (int h = hs; h < he; ++h) {
        const float* row = base + h * WW;
        #pragma unroll 1
        for (int w = ws; w < we; ++w) {
            m = fmaxf(m, __ldg(row + w));
        }
    }
    out[o] = m;
}

extern "C" void kernel_launch(void* const* d_in, const int* in_sizes, int n_in,
                              void* d_out, int out_size) {
    const float* images  = (const float*)d_in[0];
    const float* rois    = (const float*)d_in[1];
    const int*   roi_idx = (const int*)d_in[2];
    float*       out     = (float*)d_out;

    const int total = RR * CC * SS * SS;   // 3,211,264
    int threads = 256;
    int blocks = (total + threads - 1) / threads;
    SlowROIPool_43705587204143_kernel<<<blocks, threads>>>(images, rois, roi_idx, out);
}

// round 4
// speedup vs baseline: 1.2655x; 1.2655x over previous
#include <cuda_runtime.h>
#include <math.h>
#include <float.h>

// Shapes fixed by setup_inputs:
//   images: [N=4, C=256, H=50, W=50] fp32
//   rois:   [R=256, 4] fp32
//   roi_idx:[R=256] int32
//   out:    [R=256, C=256, 7, 7] fp32
#define CC 256
#define HH 50
#define WW 50
#define RR 256
#define SS 7
#define HW (HH * WW)

// Block = one ROI x one 32-channel chunk. blockDim = (49, 8) = 392 threads.
// threadIdx.x = output bin (i*7+j), threadIdx.y = channel lane; each thread
// covers channels c0, c0+8, c0+16, c0+24 (pairs for MLP).
__global__ __launch_bounds__(392)
void SlowROIPool_43705587204143_kernel(const float* __restrict__ images,
                                       const float* __restrict__ rois,
                                       const int*   __restrict__ roi_idx,
                                       float*       __restrict__ out) {
    const int r     = blockIdx.x >> 3;
    const int chunk = blockIdx.x & 7;
    const int tx    = threadIdx.x;              // 0..48
    const int ty    = threadIdx.y;              // 0..7
    const int tid   = tx + 49 * ty;

    __shared__ int s_ws[SS], s_we[SS], s_hs[SS], s_he[SS];
    __shared__ int s_n;

    if (tid < SS) {
        // ROI geometry — identical fp32 ops to the reference.
        float4 rb = __ldg((const float4*)rois + r);
        int x1 = (int)floorf(rb.x * (float)WW);
        int y1 = (int)floorf(rb.y * (float)HH);
        int x2 = (int)ceilf (rb.z * (float)WW);
        int y2 = (int)ceilf (rb.w * (float)HH);
        int sw = x2 - x1;
        int sh = y2 - y1;
        // PyTorch adaptive bins: start = lo + floor(k*sz/S), end = lo + ceil((k+1)*sz/S)
        s_ws[tid] = x1 + (tid * sw) / SS;
        s_we[tid] = x1 + ((tid + 1) * sw + SS - 1) / SS;
        s_hs[tid] = y1 + (tid * sh) / SS;
        s_he[tid] = y1 + ((tid + 1) * sh + SS - 1) / SS;
    }
    if (tid == SS) s_n = __ldg(roi_idx + r);
    __syncthreads();

    const int i  = tx / SS;
    const int j  = tx - SS * i;
    const int ws = s_ws[j], we = s_we[j];
    const int hs = s_hs[i], he = s_he[i];

    const float* base_n = images + (size_t)s_n * (CC * HW);
    const int    c0     = chunk * 32 + ty;
    float*       outp   = out + (size_t)r * (CC * SS * SS) + tx;

    #pragma unroll
    for (int kk = 0; kk < 2; ++kk) {
        const int cA = c0 + 16 * kk;
        const int cB = cA + 8;
        const float* baseA = base_n + (size_t)cA * HW;
        const float* baseB = base_n + (size_t)cB * HW;

        float mA = -FLT_MAX;
        float mB = -FLT_MAX;
        for (int h = hs; h < he; ++h) {
            const float* rowA = baseA + h * WW;
            const float* rowB = baseB + h * WW;
            #pragma unroll 1
            for (int w = ws; w < we; ++w) {
                mA = fmaxf(mA, __ldg(rowA + w));
                mB = fmaxf(mB, __ldg(rowB + w));
            }
        }
        outp[(size_t)cA * (SS * SS)] = mA;
        outp[(size_t)cB * (SS * SS)] = mB;
    }
}

extern "C" void kernel_launch(void* const* d_in, const int* in_sizes, int n_in,
                              void* d_out, int out_size) {
    const float* images  = (const float*)d_in[0];
    const float* rois    = (const float*)d_in[1];
    const int*   roi_idx = (const int*)d_in[2];
    float*       out     = (float*)d_out;

    dim3 block(49, 8);
    dim3 grid(RR * 8);   // 2048 blocks: (roi, 32-channel chunk)
    SlowROIPool_43705587204143_kernel<<<grid, block>>>(images, rois, roi_idx, out);
}